// round 6
// baseline (speedup 1.0000x reference)
#include <cuda_runtime.h>
#include <stdint.h>

#define BB 128
#define TT 1024
#define DD 256
#define UU 48

// Scratch (allocation-free rule: __device__ globals)
__device__ float         g_logits[(size_t)BB * TT * UU];     // 25.2 MB
__device__ unsigned char g_bp[(size_t)(TT - 1) * BB * UU];   // 6.29 MB
__device__ int           g_last[BB];

#define ADD_F32X2(out, a, b) \
    asm("add.rn.f32x2 %0, %1, %2;" : "=l"(out) : "l"(a), "l"(b))

// ---------------------------------------------------------------------------
// Kernel 1: logits = x @ kernel + bias   (131072 x 48 x 256, fp32)
// Measured 105.5us ~= 1.12x the fp32 FFMA chip floor; unchanged.
// ---------------------------------------------------------------------------
#define GR 128
#define GK 64
#define XPAD 130

__global__ __launch_bounds__(128) void gemm_kernel(const float* __restrict__ x,
                                                   const float* __restrict__ w,
                                                   const float* __restrict__ bias) {
    __shared__ float xs[GK][XPAD];  // [k][row]
    __shared__ float ws[GK][UU];    // [k][col]

    const int tid = threadIdx.x;
    const int tc  = tid & 3;    // cols tc*12 .. +11
    const int tr  = tid >> 2;   // rows tr*4 .. +3
    const size_t row0 = (size_t)blockIdx.x * GR;

    float acc[4][12];
#pragma unroll
    for (int i = 0; i < 4; i++)
#pragma unroll
        for (int j = 0; j < 12; j++) acc[i][j] = 0.0f;

    for (int kc = 0; kc < DD; kc += GK) {
        const float4* wg = (const float4*)(w + (size_t)kc * UU);
        float4* wsv = (float4*)&ws[0][0];
#pragma unroll
        for (int i = 0; i < 6; i++) wsv[tid + i * 128] = wg[tid + i * 128];

#pragma unroll
        for (int i = 0; i < 16; i++) {
            int j  = tid + i * 128;
            int r  = j >> 4;
            int k4 = j & 15;
            float4 f = *(const float4*)(x + (row0 + (size_t)r) * DD + kc + k4 * 4);
            xs[k4 * 4 + 0][r] = f.x;
            xs[k4 * 4 + 1][r] = f.y;
            xs[k4 * 4 + 2][r] = f.z;
            xs[k4 * 4 + 3][r] = f.w;
        }
        __syncthreads();

#pragma unroll 4
        for (int k = 0; k < GK; k++) {
            float xv[4], wv[12];
            float2 xa = *(const float2*)&xs[k][tr * 4];
            float2 xb = *(const float2*)&xs[k][tr * 4 + 2];
            xv[0] = xa.x; xv[1] = xa.y; xv[2] = xb.x; xv[3] = xb.y;
#pragma unroll
            for (int q = 0; q < 3; q++) {
                float4 wq = *(const float4*)&ws[k][tc * 12 + q * 4];
                wv[q * 4 + 0] = wq.x; wv[q * 4 + 1] = wq.y;
                wv[q * 4 + 2] = wq.z; wv[q * 4 + 3] = wq.w;
            }
#pragma unroll
            for (int i = 0; i < 4; i++)
#pragma unroll
                for (int j = 0; j < 12; j++) acc[i][j] += xv[i] * wv[j];
        }
        __syncthreads();
    }

    float bv[12];
#pragma unroll
    for (int j = 0; j < 12; j++) bv[j] = bias[tc * 12 + j];

#pragma unroll
    for (int i = 0; i < 4; i++) {
        size_t r = row0 + tr * 4 + i;
        float* o = g_logits + r * UU + tc * 12;
#pragma unroll
        for (int j = 0; j < 12; j++) o[j] = acc[i][j] + bv[j];
    }
}

// ---------------------------------------------------------------------------
// Index-argmax over 24 candidates (half range), first-index tie-break
// (strict-greater replacement, left operand covers smaller indices).
// ---------------------------------------------------------------------------
__device__ __forceinline__ void argmax24(const unsigned long long (&c)[12],
                                         float& bvo, int& bio) {
    float v[12];
    int   ix[12];
#pragma unroll
    for (int j = 0; j < 12; j++) {
        float lo = __uint_as_float((unsigned)(c[j] & 0xFFFFFFFFull));
        float hi = __uint_as_float((unsigned)(c[j] >> 32));
        v[j]  = fmaxf(lo, hi);
        ix[j] = (hi > lo) ? (2 * j + 1) : (2 * j);
    }
#pragma unroll
    for (int j = 0; j < 6; j++) {
        float a = v[2 * j], b = v[2 * j + 1];
        v[j]  = fmaxf(a, b);
        ix[j] = (b > a) ? ix[2 * j + 1] : ix[2 * j];
    }
#pragma unroll
    for (int j = 0; j < 3; j++) {
        float a = v[2 * j], b = v[2 * j + 1];
        v[j]  = fmaxf(a, b);
        ix[j] = (b > a) ? ix[2 * j + 1] : ix[2 * j];
    }
    float m01 = fmaxf(v[0], v[1]);
    int  i01  = (v[1] > v[0]) ? ix[1] : ix[0];
    bvo = fmaxf(m01, v[2]);
    bio = (v[2] > m01) ? ix[2] : i01;
}

// ---------------------------------------------------------------------------
// Kernel 2: Viterbi forward, 2 batch chains per block (amortize the per-step
// barrier/chain latency). 320 threads = 2 x 160; per batch:
//   local tid <  64 (2 warps): VALUE recurrence, pure-fmaxf tree.
//   local tid >= 64 (3 warps): INDEX extraction + bp store, off-chain.
// One shared __syncthreads per step advances both chains.
// ---------------------------------------------------------------------------
#define NB 2

__global__ __launch_bounds__(160 * NB) void viterbi_fwd(const float* __restrict__ trans) {
    const int tid = threadIdx.x;
    const int bl  = tid / 160;            // batch slot in block (warp-aligned: 5 warps each)
    const int lt  = tid - bl * 160;       // local tid within batch group
    const int b   = blockIdx.x * NB + bl;

    __shared__ __align__(16) float st[2][NB][UU];

    const bool is_val = (lt < 64);
    const bool val_act = (lt < UU);

    // ---- value-thread setup ----
    const int uv = val_act ? lt : (UU - 1);
    unsigned long long trv[24];
    float f0, f1, f2, f3;
    const float* lg = g_logits + (size_t)b * TT * UU + uv;
    if (is_val) {
#pragma unroll
        for (int j = 0; j < 24; j++) {
            unsigned lo = __float_as_uint(trans[(2 * j) * UU + uv]);
            unsigned hi = __float_as_uint(trans[(2 * j + 1) * UU + uv]);
            trv[j] = (unsigned long long)lo | ((unsigned long long)hi << 32);
        }
        if (val_act) st[0][bl][lt] = lg[0];
        f0 = lg[(size_t)1 * UU];
        f1 = lg[(size_t)2 * UU];
        f2 = lg[(size_t)3 * UU];
        f3 = lg[(size_t)4 * UU];
    }

    // ---- index-thread setup ----
    const int t2 = lt - 64;               // 0..95 when index thread
    const int ui = is_val ? 0 : (t2 >> 1);
    const int h  = is_val ? 0 : (t2 & 1);
    const int base = 24 * h;
    unsigned long long tri[12];
    if (!is_val) {
#pragma unroll
        for (int j = 0; j < 12; j++) {
            unsigned lo = __float_as_uint(trans[(base + 2 * j) * UU + ui]);
            unsigned hi = __float_as_uint(trans[(base + 2 * j + 1) * UU + ui]);
            tri[j] = (unsigned long long)lo | ((unsigned long long)hi << 32);
        }
    }
    unsigned char* bpb = g_bp + (size_t)b * UU + ui;

    __syncthreads();

    int p = 0;
    for (int t = 1; t < TT; ++t) {
        if (is_val) {
            float cur = f0;
            f0 = f1;
            f1 = f2;
            f2 = f3;
            int tn = t + 4;
            if (tn > TT - 1) tn = TT - 1;
            f3 = lg[(size_t)tn * UU];

            unsigned long long c[24];
#pragma unroll
            for (int m = 0; m < 12; m++) {
                ulonglong2 s = *(const ulonglong2*)&st[p][bl][4 * m];
                ADD_F32X2(c[2 * m + 0], s.x, trv[2 * m + 0]);
                ADD_F32X2(c[2 * m + 1], s.y, trv[2 * m + 1]);
            }
            float v[24];
#pragma unroll
            for (int j = 0; j < 24; j++) {
                float lo = __uint_as_float((unsigned)(c[j] & 0xFFFFFFFFull));
                float hi = __uint_as_float((unsigned)(c[j] >> 32));
                v[j] = fmaxf(lo, hi);
            }
#pragma unroll
            for (int j = 0; j < 12; j++) v[j] = fmaxf(v[2 * j], v[2 * j + 1]);
#pragma unroll
            for (int j = 0; j < 6; j++)  v[j] = fmaxf(v[2 * j], v[2 * j + 1]);
#pragma unroll
            for (int j = 0; j < 3; j++)  v[j] = fmaxf(v[2 * j], v[2 * j + 1]);
            float bv = fmaxf(fmaxf(v[0], v[1]), v[2]);

            if (val_act) st[p ^ 1][bl][lt] = cur + bv;
        } else {
            unsigned long long c[12];
#pragma unroll
            for (int m = 0; m < 6; m++) {
                ulonglong2 s = *(const ulonglong2*)&st[p][bl][base + 4 * m];
                ADD_F32X2(c[2 * m + 0], s.x, tri[2 * m + 0]);
                ADD_F32X2(c[2 * m + 1], s.y, tri[2 * m + 1]);
            }
            float bv;
            int bi;
            argmax24(c, bv, bi);
            bi += base;

            float ov = __shfl_down_sync(0xFFFFFFFFu, bv, 1);
            int   oi = __shfl_down_sync(0xFFFFFFFFu, bi, 1);
            int   mi = (ov > bv) ? oi : bi;

            if (h == 0) bpb[(size_t)(t - 1) * BB * UU] = (unsigned char)mi;
        }
        __syncthreads();
        p ^= 1;
    }

    if (lt == 0) {
        float bv = st[p][bl][0];
        int bi = 0;
#pragma unroll
        for (int i = 1; i < UU; i++) {
            if (st[p][bl][i] > bv) { bv = st[p][bl][i]; bi = i; }
        }
        g_last[b] = bi;
    }
}

// ---------------------------------------------------------------------------
// Kernel 3: backtrack + emit. 128 blocks (one batch each), 256 threads.
// Stage the batch's full bp column (1023 x 48 B) into SMEM in parallel,
// then walk the chain with a branchless LDS.U8 per step.
// ---------------------------------------------------------------------------
__global__ __launch_bounds__(256) void backtrack_kernel(float* __restrict__ out) {
    __shared__ unsigned char sbp[(TT - 1) * UU];  // 49104 B

    const int b = blockIdx.x;
    const int tid = threadIdx.x;

    const unsigned char* gsrc = g_bp + (size_t)b * UU;
    for (int idx = tid; idx < (TT - 1) * 3; idx += 256) {
        int s = idx / 3;
        int w = idx % 3;
        uint4 v = *(const uint4*)(gsrc + (size_t)s * BB * UU + w * 16);
        *(uint4*)(sbp + s * UU + w * 16) = v;
    }
    __syncthreads();

    if (tid != 0) return;

    int tag = g_last[b];
    float* ob = out + (size_t)b * TT;
    ob[TT - 1] = (float)tag;

    int off = (TT - 2) * UU;
#pragma unroll 8
    for (int s = TT - 2; s >= 0; --s) {
        tag = sbp[off + tag];
        ob[s] = (float)tag;
        off -= UU;
    }
}

// ---------------------------------------------------------------------------
extern "C" void kernel_launch(void* const* d_in, const int* in_sizes, int n_in,
                              void* d_out, int out_size) {
    const float* x     = (const float*)d_in[0];  // (128,1024,256)
    const float* kern  = (const float*)d_in[1];  // (256,48)
    const float* bias  = (const float*)d_in[2];  // (48,)
    const float* chain = (const float*)d_in[3];  // (48,48)
    float* out = (float*)d_out;                  // (128,1024) float32

    gemm_kernel<<<(BB * TT) / GR, 128>>>(x, kern, bias);
    viterbi_fwd<<<BB / NB, 160 * NB>>>(chain);
    backtrack_kernel<<<BB, 256>>>(out);
}